// round 7
// baseline (speedup 1.0000x reference)
#include <cuda_runtime.h>

#define N_NODES 50000
#define N_EDGES 800000
#define H 64
#define RES 0.5f
#define INV_1PRES (1.0f / (1.0f + RES))

// ---------------- device scratch (no allocation allowed) ----------------
__device__ float g_s1[N_NODES];
__device__ float g_s2[N_NODES];      // att_b folded in
__device__ float g_rowsum[N_NODES];
__device__ float g_expatt[N_EDGES];

typedef unsigned long long u64;

__device__ __forceinline__ u64 pack2(float lo, float hi) {
    u64 r;
    asm("mov.b64 %0, {%1, %2};" : "=l"(r) : "f"(lo), "f"(hi));
    return r;
}
__device__ __forceinline__ void unpack2(u64 v, float& lo, float& hi) {
    asm("mov.b64 {%0, %1}, %2;" : "=f"(lo), "=f"(hi) : "l"(v));
}
__device__ __forceinline__ u64 ffma2(u64 a, u64 b, u64 c) {
    u64 d;
    asm("fma.rn.f32x2 %0, %1, %2, %3;" : "=l"(d) : "l"(a), "l"(b), "l"(c));
    return d;
}

// ------------------------------------------------------------------------
// Kernel 1: tiled dual-GEMM for per-node attention scalars.
//   Block(256) = 64-node tile, 4 blocks/SM (launch_bounds caps regs at 64).
//   Thread (ng=tid&31, cg=tid>>5): 2 nodes x 8 cols x 2 mats = 16 f32x2
//   accumulators. Single k-pass over both weight matrices.
//   Conflict-free smem transpose; weight LDS warp-uniform broadcast.
// ------------------------------------------------------------------------
__global__ __launch_bounds__(256, 4)
void gat_node_kernel(const float* __restrict__ embeds,
                     const float* __restrict__ W1, const float* __restrict__ b1,
                     const float* __restrict__ W2, const float* __restrict__ b2,
                     const float* __restrict__ att_w, const float* __restrict__ att_b) {
    extern __shared__ float smem[];
    float* Xs  = smem;            // [64 k][64 nodes] = 4096 floats (16KB)
    float* W1s = smem + 4096;     // [64 k][64 j]     = 4096 floats (16KB)
    float* W2s = smem + 8192;     // 16KB

    const int tid = threadIdx.x;
    const int tile = blockIdx.x * 64;
    const int ng = tid & 31;   // nodes 2*ng, 2*ng+1
    const int cg = tid >> 5;   // cols cg*8 .. cg*8+7 (uniform per warp)

    // ---- load W1, W2 (coalesced float4 copies) ----
    {
        const float4* w1g = (const float4*)W1;
        const float4* w2g = (const float4*)W2;
        float4* w1s = (float4*)W1s;
        float4* w2s = (float4*)W2s;
#pragma unroll
        for (int i = 0; i < 4; i++) {
            int idx = tid + i * 256;
            w1s[idx] = w1g[idx];
            w2s[idx] = w2g[idx];
        }
    }
    // ---- load X tile -> k-major smem, conflict-free STS ----
    // nl = idx & 63 (consecutive lanes = consecutive nodes -> coalesced STS)
    {
#pragma unroll
        for (int i = 0; i < 4; i++) {
            int idx = tid + i * 256;          // [0, 1024)
            int nl = idx & 63;
            int k4 = idx >> 6;                // 0..15
            int node = tile + nl;
            if (node > N_NODES - 1) node = N_NODES - 1;
            float4 v = __ldg((const float4*)(embeds + (size_t)node * H + k4 * 4));
            Xs[(4 * k4 + 0) * 64 + nl] = v.x;
            Xs[(4 * k4 + 1) * 64 + nl] = v.y;
            Xs[(4 * k4 + 2) * 64 + nl] = v.z;
            Xs[(4 * k4 + 3) * 64 + nl] = v.w;
        }
    }
    __syncthreads();

    // ---- main loop: 16 f32x2 accumulators (2 nodes x 4 pairs x 2 mats) ----
    u64 acc1[2][4], acc2[2][4];
#pragma unroll
    for (int n = 0; n < 2; n++)
#pragma unroll
        for (int j = 0; j < 4; j++) { acc1[n][j] = 0ULL; acc2[n][j] = 0ULL; }

#pragma unroll 8
    for (int k = 0; k < 64; k++) {
        float2 xv = *(const float2*)(Xs + k * 64 + ng * 2);
        u64 xp0 = pack2(xv.x, xv.x);
        u64 xp1 = pack2(xv.y, xv.y);
        const float* w1r = W1s + k * 64 + cg * 8;   // warp-uniform broadcast
        const float* w2r = W2s + k * 64 + cg * 8;
        ulonglong2 w1a = *(const ulonglong2*)(w1r);
        ulonglong2 w1b = *(const ulonglong2*)(w1r + 4);
        ulonglong2 w2a = *(const ulonglong2*)(w2r);
        ulonglong2 w2b = *(const ulonglong2*)(w2r + 4);
        acc1[0][0] = ffma2(xp0, w1a.x, acc1[0][0]);
        acc1[0][1] = ffma2(xp0, w1a.y, acc1[0][1]);
        acc1[0][2] = ffma2(xp0, w1b.x, acc1[0][2]);
        acc1[0][3] = ffma2(xp0, w1b.y, acc1[0][3]);
        acc2[0][0] = ffma2(xp0, w2a.x, acc2[0][0]);
        acc2[0][1] = ffma2(xp0, w2a.y, acc2[0][1]);
        acc2[0][2] = ffma2(xp0, w2b.x, acc2[0][2]);
        acc2[0][3] = ffma2(xp0, w2b.y, acc2[0][3]);
        acc1[1][0] = ffma2(xp1, w1a.x, acc1[1][0]);
        acc1[1][1] = ffma2(xp1, w1a.y, acc1[1][1]);
        acc1[1][2] = ffma2(xp1, w1b.x, acc1[1][2]);
        acc1[1][3] = ffma2(xp1, w1b.y, acc1[1][3]);
        acc2[1][0] = ffma2(xp1, w2a.x, acc2[1][0]);
        acc2[1][1] = ffma2(xp1, w2a.y, acc2[1][1]);
        acc2[1][2] = ffma2(xp1, w2b.x, acc2[1][2]);
        acc2[1][3] = ffma2(xp1, w2b.y, acc2[1][3]);
    }

    // ---- epilogue: bias + relu + att_w dot over this thread's 8 cols ----
    float p1[2], p2[2];
    {
        float b1v[8], b2v[8], aw1[8], aw2[8];
        float4 t;
        t = __ldg((const float4*)(b1 + cg * 8));     b1v[0]=t.x;b1v[1]=t.y;b1v[2]=t.z;b1v[3]=t.w;
        t = __ldg((const float4*)(b1 + cg * 8 + 4)); b1v[4]=t.x;b1v[5]=t.y;b1v[6]=t.z;b1v[7]=t.w;
        t = __ldg((const float4*)(b2 + cg * 8));     b2v[0]=t.x;b2v[1]=t.y;b2v[2]=t.z;b2v[3]=t.w;
        t = __ldg((const float4*)(b2 + cg * 8 + 4)); b2v[4]=t.x;b2v[5]=t.y;b2v[6]=t.z;b2v[7]=t.w;
        t = __ldg((const float4*)(att_w + cg * 8));      aw1[0]=t.x;aw1[1]=t.y;aw1[2]=t.z;aw1[3]=t.w;
        t = __ldg((const float4*)(att_w + cg * 8 + 4));  aw1[4]=t.x;aw1[5]=t.y;aw1[6]=t.z;aw1[7]=t.w;
        t = __ldg((const float4*)(att_w + H + cg * 8));     aw2[0]=t.x;aw2[1]=t.y;aw2[2]=t.z;aw2[3]=t.w;
        t = __ldg((const float4*)(att_w + H + cg * 8 + 4)); aw2[4]=t.x;aw2[5]=t.y;aw2[6]=t.z;aw2[7]=t.w;
#pragma unroll
        for (int n = 0; n < 2; n++) {
            float s1 = 0.f, s2 = 0.f;
#pragma unroll
            for (int j = 0; j < 4; j++) {
                float a, b;
                unpack2(acc1[n][j], a, b);
                s1 += fmaxf(a + b1v[2 * j], 0.f) * aw1[2 * j]
                    + fmaxf(b + b1v[2 * j + 1], 0.f) * aw1[2 * j + 1];
                unpack2(acc2[n][j], a, b);
                s2 += fmaxf(a + b2v[2 * j], 0.f) * aw2[2 * j]
                    + fmaxf(b + b2v[2 * j + 1], 0.f) * aw2[2 * j + 1];
            }
            p1[n] = s1;
            p2[n] = s2;
        }
    }

    // ---- cross-colgroup reduction via smem (reuse Xs) ----
    __syncthreads();
    float* red1 = Xs;           // [64 nodes][8 cg]
    float* red2 = Xs + 512;
#pragma unroll
    for (int n = 0; n < 2; n++) {
        int nl = ng * 2 + n;
        red1[nl * 8 + cg] = p1[n];
        red2[nl * 8 + cg] = p2[n];
    }
    __syncthreads();

    if (tid < 64) {
        int node = tile + tid;
        if (node < N_NODES) {
            float s1 = 0.f, s2 = 0.f;
#pragma unroll
            for (int c = 0; c < 8; c++) { s1 += red1[tid * 8 + c]; s2 += red2[tid * 8 + c]; }
            g_s1[node] = s1;
            g_s2[node] = s2 + __ldg(att_b);
            g_rowsum[node] = 0.f;
        }
    }
}

// ------------------------------------------------------------------------
// Kernel 2: per-edge exp(att) + segment-sum; also zeroes out_part
// (exactly one float4 per thread: 800k threads x 4 = 3.2M floats = N*H).
// ------------------------------------------------------------------------
__global__ __launch_bounds__(256)
void gat_edge_att_kernel(const int* __restrict__ edge_index,
                         float* __restrict__ out_part) {
    int e = blockIdx.x * blockDim.x + threadIdx.x;
    if (e >= N_EDGES) return;

    ((float4*)out_part)[e] = make_float4(0.f, 0.f, 0.f, 0.f);

    int r = __ldg(edge_index + e);
    int c = __ldg(edge_index + N_EDGES + e);
    float ea = __expf(__ldg(g_s1 + r) + __ldg(g_s2 + c));
    g_expatt[e] = ea;
    atomicAdd(&g_rowsum[r], ea);
}

// ------------------------------------------------------------------------
// Kernel 3: per-edge value + SpMM scatter (16 threads/edge, float4 red).
// ------------------------------------------------------------------------
__global__ __launch_bounds__(256)
void gat_edge_spmm_kernel(const int* __restrict__ edge_index,
                          const float* __restrict__ adj_values,
                          const float* __restrict__ embeds,
                          float* __restrict__ values,
                          float* __restrict__ out_part) {
    unsigned gid = blockIdx.x * blockDim.x + threadIdx.x;
    unsigned e = gid >> 4;
    if (e >= N_EDGES) return;
    unsigned sub = gid & 15u;

    int r = __ldg(edge_index + e);
    int c = __ldg(edge_index + N_EDGES + e);
    float ea = __ldg(g_expatt + e);
    float rs = __ldg(g_rowsum + r) + 1e-6f;
    float v = (ea / rs + RES * __ldg(adj_values + e)) * INV_1PRES;
    if (sub == 0) values[e] = v;

    float4 ev = __ldg((const float4*)(embeds + (size_t)c * H + sub * 4));
    float* dst = out_part + (size_t)r * H + sub * 4;
    asm volatile("red.global.add.v4.f32 [%0], {%1, %2, %3, %4};"
                 :: "l"(dst), "f"(ev.x * v), "f"(ev.y * v), "f"(ev.z * v), "f"(ev.w * v)
                 : "memory");
}

// ------------------------------------------------------------------------
extern "C" void kernel_launch(void* const* d_in, const int* in_sizes, int n_in,
                              void* d_out, int out_size) {
    const int*   edge_index = (const int*)d_in[0];
    const float* adj_values = (const float*)d_in[1];
    const float* embeds     = (const float*)d_in[2];
    const float* W1         = (const float*)d_in[3];
    const float* b1         = (const float*)d_in[4];
    const float* W2         = (const float*)d_in[5];
    const float* b2         = (const float*)d_in[6];
    const float* att_w      = (const float*)d_in[7];
    const float* att_b      = (const float*)d_in[8];

    float* values   = (float*)d_out;            // [E]
    float* out_part = (float*)d_out + N_EDGES;  // [N, H]

    static bool attr_done = false;
    if (!attr_done) {
        cudaFuncSetAttribute(gat_node_kernel,
                             cudaFuncAttributeMaxDynamicSharedMemorySize, 49152);
        attr_done = true;
    }

    gat_node_kernel<<<(N_NODES + 63) / 64, 256, 49152>>>(
        embeds, W1, b1, W2, b2, att_w, att_b);

    gat_edge_att_kernel<<<(N_EDGES + 255) / 256, 256>>>(edge_index, out_part);

    gat_edge_spmm_kernel<<<(N_EDGES * 16 + 255) / 256, 256>>>(
        edge_index, adj_values, embeds, values, out_part);
}

// round 8
// speedup vs baseline: 1.1522x; 1.1522x over previous
#include <cuda_runtime.h>
#include <cstdint>

#define N_NODES 50000
#define N_EDGES 800000
#define H 64
#define RES 0.5f
#define INV_1PRES (1.0f / (1.0f + RES))

#define XS_STRIDE 68   // padded: A-frag LDS conflict-free (4r+q spans banks)
#define WS_STRIDE 68   // padded: B-frag LDS <=2-way

// ---------------- device scratch (no allocation allowed) ----------------
__device__ float g_s1[N_NODES];
__device__ float g_s2[N_NODES];      // att_b folded in
__device__ float g_rowsum[N_NODES];
__device__ float g_expatt[N_EDGES];

__device__ __forceinline__ uint32_t cvt_tf32(float x) {
    uint32_t r;
    asm("cvt.rna.tf32.f32 %0, %1;" : "=r"(r) : "f"(x));
    return r;
}

__device__ __forceinline__ void mma_tf32(float c[4], const uint32_t a[4],
                                         uint32_t b0, uint32_t b1) {
    asm volatile(
        "mma.sync.aligned.m16n8k8.row.col.f32.tf32.tf32.f32 "
        "{%0,%1,%2,%3}, {%4,%5,%6,%7}, {%8,%9}, {%0,%1,%2,%3};"
        : "+f"(c[0]), "+f"(c[1]), "+f"(c[2]), "+f"(c[3])
        : "r"(a[0]), "r"(a[1]), "r"(a[2]), "r"(a[3]), "r"(b0), "r"(b1));
}

// ------------------------------------------------------------------------
// Kernel 1: per-node attention scalars via tensor-core tf32 MMA.
//   Block(256)=8 warps, 128-node tile. Warp w owns nodes w*16..w*16+15,
//   all 64 output cols, both W1 and W2 (16 m16n8 C-fragments).
//   k=64 in 8 steps of m16n8k8. Epilogue: relu+att_w dot in-fragment,
//   quad shfl reduce, direct write of s1/s2. Zeroes g_rowsum.
// ------------------------------------------------------------------------
__global__ __launch_bounds__(256)
void gat_node_kernel(const float* __restrict__ embeds,
                     const float* __restrict__ W1, const float* __restrict__ b1,
                     const float* __restrict__ W2, const float* __restrict__ b2,
                     const float* __restrict__ att_w, const float* __restrict__ att_b) {
    extern __shared__ float smem[];
    float* Xs  = smem;                               // [128][XS_STRIDE]
    float* W1s = smem + 128 * XS_STRIDE;             // [64][WS_STRIDE]
    float* W2s = W1s + 64 * WS_STRIDE;

    const int tid  = threadIdx.x;
    const int warp = tid >> 5;
    const int lane = tid & 31;
    const int g    = lane >> 2;   // group id (row within fragment)
    const int q    = lane & 3;    // thread-in-group (k / col pairs)
    const int tile = blockIdx.x * 128;

    // ---- load W1, W2 into padded smem (coalesced float4 reads) ----
#pragma unroll
    for (int i = 0; i < 4; i++) {
        int idx = tid + i * 256;            // [0,1024): 64 rows x 16 float4
        int k  = idx >> 4;
        int j4 = idx & 15;
        float4 v1 = __ldg((const float4*)(W1 + k * H) + j4);
        float4 v2 = __ldg((const float4*)(W2 + k * H) + j4);
        float* d1 = W1s + k * WS_STRIDE + j4 * 4;
        float* d2 = W2s + k * WS_STRIDE + j4 * 4;
        d1[0] = v1.x; d1[1] = v1.y; d1[2] = v1.z; d1[3] = v1.w;
        d2[0] = v2.x; d2[1] = v2.y; d2[2] = v2.z; d2[3] = v2.w;
    }
    // ---- load X tile into padded smem ----
#pragma unroll
    for (int i = 0; i < 8; i++) {
        int idx = tid + i * 256;            // [0,2048): 128 rows x 16 float4
        int nl = idx >> 4;
        int k4 = idx & 15;
        int node = tile + nl;
        if (node > N_NODES - 1) node = N_NODES - 1;
        float4 v = __ldg((const float4*)(embeds + (size_t)node * H) + k4);
        float* d = Xs + nl * XS_STRIDE + k4 * 4;
        d[0] = v.x; d[1] = v.y; d[2] = v.z; d[3] = v.w;
    }
    __syncthreads();

    // ---- MMA mainloop: C1/C2 [8 n-tiles][4 regs] ----
    float C1[8][4], C2[8][4];
#pragma unroll
    for (int jt = 0; jt < 8; jt++)
#pragma unroll
        for (int r = 0; r < 4; r++) { C1[jt][r] = 0.f; C2[jt][r] = 0.f; }

    const float* xw = Xs + warp * 16 * XS_STRIDE;

#pragma unroll
    for (int kk = 0; kk < 8; kk++) {
        int kb = kk * 8;
        uint32_t A[4];
        A[0] = cvt_tf32(xw[g * XS_STRIDE + kb + q]);
        A[1] = cvt_tf32(xw[(g + 8) * XS_STRIDE + kb + q]);
        A[2] = cvt_tf32(xw[g * XS_STRIDE + kb + q + 4]);
        A[3] = cvt_tf32(xw[(g + 8) * XS_STRIDE + kb + q + 4]);
#pragma unroll
        for (int jt = 0; jt < 8; jt++) {
            int jb = jt * 8 + g;
            uint32_t b0 = cvt_tf32(W1s[(kb + q) * WS_STRIDE + jb]);
            uint32_t bq = cvt_tf32(W1s[(kb + q + 4) * WS_STRIDE + jb]);
            mma_tf32(C1[jt], A, b0, bq);
            b0 = cvt_tf32(W2s[(kb + q) * WS_STRIDE + jb]);
            bq = cvt_tf32(W2s[(kb + q + 4) * WS_STRIDE + jb]);
            mma_tf32(C2[jt], A, b0, bq);
        }
    }

    // ---- epilogue: bias + relu + att_w dot, in-fragment ----
    float p1lo = 0.f, p1hi = 0.f, p2lo = 0.f, p2hi = 0.f;
#pragma unroll
    for (int jt = 0; jt < 8; jt++) {
        int c0 = jt * 8 + q * 2;
        float bb0 = __ldg(b1 + c0),      bb1 = __ldg(b1 + c0 + 1);
        float aw0 = __ldg(att_w + c0),   aw1 = __ldg(att_w + c0 + 1);
        p1lo += fmaxf(C1[jt][0] + bb0, 0.f) * aw0 + fmaxf(C1[jt][1] + bb1, 0.f) * aw1;
        p1hi += fmaxf(C1[jt][2] + bb0, 0.f) * aw0 + fmaxf(C1[jt][3] + bb1, 0.f) * aw1;
        bb0 = __ldg(b2 + c0);            bb1 = __ldg(b2 + c0 + 1);
        aw0 = __ldg(att_w + H + c0);     aw1 = __ldg(att_w + H + c0 + 1);
        p2lo += fmaxf(C2[jt][0] + bb0, 0.f) * aw0 + fmaxf(C2[jt][1] + bb1, 0.f) * aw1;
        p2hi += fmaxf(C2[jt][2] + bb0, 0.f) * aw0 + fmaxf(C2[jt][3] + bb1, 0.f) * aw1;
    }
    // quad reduce (lanes 4g..4g+3 hold the 8 col-pairs of rows g / g+8)
#pragma unroll
    for (int m = 1; m <= 2; m <<= 1) {
        p1lo += __shfl_xor_sync(0xffffffffu, p1lo, m);
        p1hi += __shfl_xor_sync(0xffffffffu, p1hi, m);
        p2lo += __shfl_xor_sync(0xffffffffu, p2lo, m);
        p2hi += __shfl_xor_sync(0xffffffffu, p2hi, m);
    }

    if (q == 0) {
        float ab = __ldg(att_b);
        int node = tile + warp * 16 + g;
        if (node < N_NODES) {
            g_s1[node] = p1lo;
            g_s2[node] = p2lo + ab;
        }
        if (node + 8 < N_NODES) {
            g_s1[node + 8] = p1hi;
            g_s2[node + 8] = p2hi + ab;
        }
    }

    // zero rowsum for this tile's nodes
    if (tid < 128) {
        int node = tile + tid;
        if (node < N_NODES) g_rowsum[node] = 0.f;
    }
}

// ------------------------------------------------------------------------
// Kernel 2: per-edge exp(att) + segment-sum; also zeroes out_part
// (exactly one float4 per thread: 800k threads x 4 = 3.2M floats = N*H).
// ------------------------------------------------------------------------
__global__ __launch_bounds__(256)
void gat_edge_att_kernel(const int* __restrict__ edge_index,
                         float* __restrict__ out_part) {
    int e = blockIdx.x * blockDim.x + threadIdx.x;
    if (e >= N_EDGES) return;

    ((float4*)out_part)[e] = make_float4(0.f, 0.f, 0.f, 0.f);

    int r = __ldg(edge_index + e);
    int c = __ldg(edge_index + N_EDGES + e);
    float ea = __expf(__ldg(g_s1 + r) + __ldg(g_s2 + c));
    g_expatt[e] = ea;
    atomicAdd(&g_rowsum[r], ea);
}

// ------------------------------------------------------------------------
// Kernel 3: per-edge value + SpMM scatter (16 threads/edge, float4 red).
// ------------------------------------------------------------------------
__global__ __launch_bounds__(256)
void gat_edge_spmm_kernel(const int* __restrict__ edge_index,
                          const float* __restrict__ adj_values,
                          const float* __restrict__ embeds,
                          float* __restrict__ values,
                          float* __restrict__ out_part) {
    unsigned gid = blockIdx.x * blockDim.x + threadIdx.x;
    unsigned e = gid >> 4;
    if (e >= N_EDGES) return;
    unsigned sub = gid & 15u;

    int r = __ldg(edge_index + e);
    int c = __ldg(edge_index + N_EDGES + e);
    float ea = __ldg(g_expatt + e);
    float rs = __ldg(g_rowsum + r) + 1e-6f;
    float v = (ea / rs + RES * __ldg(adj_values + e)) * INV_1PRES;
    if (sub == 0) values[e] = v;

    float4 ev = __ldg((const float4*)(embeds + (size_t)c * H + sub * 4));
    float* dst = out_part + (size_t)r * H + sub * 4;
    asm volatile("red.global.add.v4.f32 [%0], {%1, %2, %3, %4};"
                 :: "l"(dst), "f"(ev.x * v), "f"(ev.y * v), "f"(ev.z * v), "f"(ev.w * v)
                 : "memory");
}

// ------------------------------------------------------------------------
extern "C" void kernel_launch(void* const* d_in, const int* in_sizes, int n_in,
                              void* d_out, int out_size) {
    const int*   edge_index = (const int*)d_in[0];
    const float* adj_values = (const float*)d_in[1];
    const float* embeds     = (const float*)d_in[2];
    const float* W1         = (const float*)d_in[3];
    const float* b1         = (const float*)d_in[4];
    const float* W2         = (const float*)d_in[5];
    const float* b2         = (const float*)d_in[6];
    const float* att_w      = (const float*)d_in[7];
    const float* att_b      = (const float*)d_in[8];

    float* values   = (float*)d_out;            // [E]
    float* out_part = (float*)d_out + N_EDGES;  // [N, H]

    const int smem_bytes = (128 * XS_STRIDE + 2 * 64 * WS_STRIDE) * 4;  // 69632

    static bool attr_done = false;
    if (!attr_done) {
        cudaFuncSetAttribute(gat_node_kernel,
                             cudaFuncAttributeMaxDynamicSharedMemorySize, smem_bytes);
        attr_done = true;
    }

    gat_node_kernel<<<(N_NODES + 127) / 128, 256, smem_bytes>>>(
        embeds, W1, b1, W2, b2, att_w, att_b);

    gat_edge_att_kernel<<<(N_EDGES + 255) / 256, 256>>>(edge_index, out_part);

    gat_edge_spmm_kernel<<<(N_EDGES * 16 + 255) / 256, 256>>>(
        edge_index, adj_values, embeds, values, out_part);
}